// round 3
// baseline (speedup 1.0000x reference)
#include <cuda_runtime.h>
#include <math.h>

// ---------------- problem constants ----------------
#define BB   2
#define SS   2048
#define DIN  2048
#define NH   16
#define KVH  4
#define HD   128
#define GRP  (NH / KVH)            // 4
#define DOUT (NH * HD)             // 2048
#define DKV  (KVH * HD)            // 512
#define BS   (BB * SS)             // 4096

// ---------------- gemm tiling ----------------
#define BM 128
#define BN 128
#define BK 8
#define TM 8
#define TN 8
#define NTHR 256

// ---------------- device scratch (allocation-free rule: __device__ globals) ----
__device__ float g_qp [(size_t)BS * DOUT];            // x@Wq   [bs, nh*hd]
__device__ float g_kp [(size_t)BS * DKV];             // x@Wk   [bs, kv*hd]
__device__ float g_vp [(size_t)BS * DKV];             // x@Wv   [bs, kv*hd]
__device__ float g_qhm[(size_t)BS * DOUT];            // q head-major [b,nh,s,hd]
__device__ float g_khm[(size_t)BS * DKV];             // k head-major [b,kv,s,hd]
__device__ float g_ctx[(size_t)BS * DOUT];            // ctx [b,s,nh*hd]
__device__ float g_scores[(size_t)BB * NH * SS * SS]; // attention scores / probs

// ---------------- shared register-tiled gemm core ----------------
// C[m0:m0+128, n0:n0+128] = alpha * A[.,0:kmax] @ op(B)
// TRANSB: B accessed as B[n][k] (row-major [N,K], i.e. compute A @ B^T)
// CAUSAL: entries with global col > global row are written as 0
template <bool TRANSB, bool CAUSAL>
__device__ __forceinline__ void gemm_core(
    const float* __restrict__ A, int lda,
    const float* __restrict__ B, int ldb,
    float* __restrict__ C, int ldc,
    int kmax, float alpha, int m0, int n0)
{
    __shared__ float As[BK][BM + 4];
    __shared__ float Bs[BK][BN + 4];

    const int tid = threadIdx.x;
    const int ty  = tid >> 4;          // 0..15
    const int tx  = tid & 15;          // 0..15

    // A load mapping: 128 rows x 8 cols, float4 per thread
    const int aRow = tid >> 1;             // 0..127
    const int aCol = (tid & 1) * 4;        // 0 or 4
    // B (NN) load mapping: 8 rows x 128 cols
    const int bRowNN = tid >> 5;           // 0..7
    const int bColNN = (tid & 31) * 4;     // 0..124
    // B (NT) load mapping: 128 rows of B (cols of op(B)) x 8 k's
    const int bColNT = tid >> 1;           // 0..127 (n index)
    const int bRowNT = (tid & 1) * 4;      // 0 or 4 (k index)

    float acc[TM][TN];
#pragma unroll
    for (int i = 0; i < TM; i++)
#pragma unroll
        for (int j = 0; j < TN; j++) acc[i][j] = 0.f;

    for (int k0 = 0; k0 < kmax; k0 += BK) {
        float4 va = *reinterpret_cast<const float4*>(
            A + (size_t)(m0 + aRow) * lda + k0 + aCol);
        As[aCol + 0][aRow] = va.x;
        As[aCol + 1][aRow] = va.y;
        As[aCol + 2][aRow] = va.z;
        As[aCol + 3][aRow] = va.w;

        if (TRANSB) {
            float4 vb = *reinterpret_cast<const float4*>(
                B + (size_t)(n0 + bColNT) * ldb + k0 + bRowNT);
            Bs[bRowNT + 0][bColNT] = vb.x;
            Bs[bRowNT + 1][bColNT] = vb.y;
            Bs[bRowNT + 2][bColNT] = vb.z;
            Bs[bRowNT + 3][bColNT] = vb.w;
        } else {
            float4 vb = *reinterpret_cast<const float4*>(
                B + (size_t)(k0 + bRowNN) * ldb + n0 + bColNN);
            *reinterpret_cast<float4*>(&Bs[bRowNN][bColNN]) = vb;
        }
        __syncthreads();

#pragma unroll
        for (int kk = 0; kk < BK; kk++) {
            float a[TM], b[TN];
            *reinterpret_cast<float4*>(&a[0]) =
                *reinterpret_cast<const float4*>(&As[kk][ty * TM]);
            *reinterpret_cast<float4*>(&a[4]) =
                *reinterpret_cast<const float4*>(&As[kk][ty * TM + 4]);
            *reinterpret_cast<float4*>(&b[0]) =
                *reinterpret_cast<const float4*>(&Bs[kk][tx * TN]);
            *reinterpret_cast<float4*>(&b[4]) =
                *reinterpret_cast<const float4*>(&Bs[kk][tx * TN + 4]);
#pragma unroll
            for (int i = 0; i < TM; i++)
#pragma unroll
                for (int j = 0; j < TN; j++)
                    acc[i][j] += a[i] * b[j];
        }
        __syncthreads();
    }

#pragma unroll
    for (int i = 0; i < TM; i++) {
        const int gr = m0 + ty * TM + i;
#pragma unroll
        for (int j = 0; j < TN; j++) {
            const int gc = n0 + tx * TN + j;
            float v = acc[i][j] * alpha;
            if (CAUSAL && gc > gr) v = 0.f;   // masked entries -> P = 0 for PV
            C[(size_t)gr * ldc + gc] = v;
        }
    }
}

// ---------------- kernels ----------------
__global__ void __launch_bounds__(NTHR, 2)
k_gemm_nn(const float* __restrict__ A, int lda,
          const float* __restrict__ B, int ldb,
          float* __restrict__ C, int ldc, int K)
{
    gemm_core<false, false>(A, lda, B, ldb, C, ldc, K, 1.0f,
                            blockIdx.y * BM, blockIdx.x * BN);
}

// scores[b,h,i,j] = (q[b,h,i,:] . k[b,kvh,j,:]) / sqrt(hd), lower-triangular only
__global__ void __launch_bounds__(NTHR, 2)
k_scores(const float* __restrict__ qhm, const float* __restrict__ khm,
         float* __restrict__ scores)
{
    const int m0 = blockIdx.y * BM;
    const int n0 = blockIdx.x * BN;
    if (n0 > m0 + BM - 1) return;          // fully-masked tile: skip
    const int bh  = blockIdx.z;
    const int b   = bh / NH;
    const int h   = bh % NH;
    const int kvh = h / GRP;
    const float* A  = qhm + (size_t)bh * SS * HD;
    const float* Bk = khm + (size_t)(b * KVH + kvh) * SS * HD;
    float* C = scores + (size_t)bh * SS * SS;
    gemm_core<true, true>(A, HD, Bk, HD, C, SS, HD,
                          0.08838834764831845f /* 1/sqrt(128) */, m0, n0);
}

// ctx[b,i,h*hd+n] = sum_{j<=...} P[b,h,i,j] * v[b,j,kvh*hd+n]  (causal K bound)
__global__ void __launch_bounds__(NTHR, 2)
k_pv(const float* __restrict__ scores, const float* __restrict__ vp,
     float* __restrict__ ctx)
{
    const int bh  = blockIdx.z;
    const int b   = bh / NH;
    const int h   = bh % NH;
    const int kvh = h / GRP;
    const int m0  = blockIdx.y * BM;
    const int n0  = blockIdx.x * BN;       // always 0 (HD == BN)
    const float* A  = scores + (size_t)bh * SS * SS;
    const float* Bv = vp + (size_t)b * SS * DKV + kvh * HD;
    float* C = ctx + (size_t)b * SS * DOUT + h * HD;
    const int kmax = min(SS, m0 + BM);     // causal: only keys <= last query in tile
    gemm_core<false, false>(A, SS, Bv, DKV, C, DOUT, kmax, 1.0f, m0, n0);
}

// fused rmsnorm + rope + transpose to head-major [b, nheads, s, hd]
__global__ void k_normrope(const float* __restrict__ in,   // [bs, nheads*hd]
                           float* __restrict__ out,        // [b, nheads, s, hd]
                           const float* __restrict__ cosb, // [s, hd]
                           const float* __restrict__ sinb,
                           const float* __restrict__ scale, // [hd]
                           int nheads)
{
    const int idx = blockIdx.x;            // bs * nheads + h
    const int h   = idx % nheads;
    const int bs  = idx / nheads;
    const int b   = bs / SS;
    const int pos = bs % SS;
    const int d   = threadIdx.x;           // 0..127

    float x = in[(size_t)bs * (nheads * HD) + h * HD + d];

    __shared__ float red[4];
    float v = x * x;
#pragma unroll
    for (int o = 16; o; o >>= 1) v += __shfl_xor_sync(0xffffffffu, v, o);
    if ((d & 31) == 0) red[d >> 5] = v;
    __syncthreads();
    const float ms = (red[0] + red[1] + red[2] + red[3]) * (1.0f / HD);
    const float xn = x * rsqrtf(ms + 1e-6f) * scale[d];

    __shared__ float sh[HD];
    sh[d] = xn;
    __syncthreads();
    const float rot = (d < HD / 2) ? -sh[d + HD / 2] : sh[d - HD / 2];
    const float o = xn * cosb[pos * HD + d] + rot * sinb[pos * HD + d];
    out[((size_t)(b * nheads + h) * SS + pos) * HD + d] = o;
}

// per-row softmax over columns [0, i]; columns (i, s) untouched (already 0)
__global__ void k_softmax(float* __restrict__ scores)
{
    const int i  = blockIdx.x;
    const int bh = blockIdx.y;
    float* row = scores + ((size_t)bh * SS + i) * SS;
    const int n = i + 1;
    const int tid = threadIdx.x;

    __shared__ float red[8];

    float m = -3.4e38f;
    for (int j = tid; j < n; j += NTHR) m = fmaxf(m, row[j]);
#pragma unroll
    for (int o = 16; o; o >>= 1) m = fmaxf(m, __shfl_xor_sync(0xffffffffu, m, o));
    if ((tid & 31) == 0) red[tid >> 5] = m;
    __syncthreads();
    float mm = red[0];
#pragma unroll
    for (int r = 1; r < 8; r++) mm = fmaxf(mm, red[r]);
    __syncthreads();

    float ssum = 0.f;
    for (int j = tid; j < n; j += NTHR) {
        const float e = __expf(row[j] - mm);
        row[j] = e;
        ssum += e;
    }
#pragma unroll
    for (int o = 16; o; o >>= 1) ssum += __shfl_xor_sync(0xffffffffu, ssum, o);
    if ((tid & 31) == 0) red[tid >> 5] = ssum;
    __syncthreads();
    float tot = 0.f;
#pragma unroll
    for (int r = 0; r < 8; r++) tot += red[r];
    const float inv = 1.0f / tot;
    for (int j = tid; j < n; j += NTHR) row[j] *= inv;
}

// ---------------- launch ----------------
extern "C" void kernel_launch(void* const* d_in, const int* in_sizes, int n_in,
                              void* d_out, int out_size)
{
    const float* x    = (const float*)d_in[0];
    // d_in[1] = mask (bool) — causal, handled structurally
    const float* cosb = (const float*)d_in[2];
    const float* sinb = (const float*)d_in[3];
    const float* Wq   = (const float*)d_in[4];
    const float* Wk   = (const float*)d_in[5];
    const float* Wv   = (const float*)d_in[6];
    const float* Wo   = (const float*)d_in[7];
    const float* qs   = (const float*)d_in[8];
    const float* ks   = (const float*)d_in[9];
    float* out = (float*)d_out;

    float *qp, *kp, *vp, *qhm, *khm, *ctx, *sc;
    cudaGetSymbolAddress((void**)&qp,  g_qp);
    cudaGetSymbolAddress((void**)&kp,  g_kp);
    cudaGetSymbolAddress((void**)&vp,  g_vp);
    cudaGetSymbolAddress((void**)&qhm, g_qhm);
    cudaGetSymbolAddress((void**)&khm, g_khm);
    cudaGetSymbolAddress((void**)&ctx, g_ctx);
    cudaGetSymbolAddress((void**)&sc,  g_scores);

    // Projections: q/k/v = x @ W
    k_gemm_nn<<<dim3(DOUT / BN, BS / BM), NTHR>>>(x, DIN, Wq, DOUT, qp, DOUT, DIN);
    k_gemm_nn<<<dim3(DKV  / BN, BS / BM), NTHR>>>(x, DIN, Wk, DKV,  kp, DKV,  DIN);
    k_gemm_nn<<<dim3(DKV  / BN, BS / BM), NTHR>>>(x, DIN, Wv, DKV,  vp, DKV,  DIN);

    // RMSNorm + RoPE + transpose to head-major
    k_normrope<<<BS * NH,  HD>>>(qp, qhm, cosb, sinb, qs, NH);
    k_normrope<<<BS * KVH, HD>>>(kp, khm, cosb, sinb, ks, KVH);

    // Attention: scores (causal lower-triangular), softmax, P@V
    k_scores <<<dim3(SS / BN, SS / BM, BB * NH), NTHR>>>(qhm, khm, sc);
    k_softmax<<<dim3(SS, BB * NH), NTHR>>>(sc);
    k_pv     <<<dim3(HD / BN, SS / BM, BB * NH), NTHR>>>(sc, vp, ctx);

    // Output projection
    k_gemm_nn<<<dim3(DIN / BN, BS / BM), NTHR>>>(ctx, DOUT, Wo, DIN, out, DIN, DOUT);
}

// round 6
// speedup vs baseline: 2.2930x; 2.2930x over previous
#include <cuda_runtime.h>
#include <cuda_bf16.h>
#include <stdint.h>
#include <math.h>

// ---------------- problem constants ----------------
#define BB   2
#define SS   2048
#define DIN  2048
#define NH   16
#define KVH  4
#define HD   128
#define GRP  (NH / KVH)            // 4
#define DOUT (NH * HD)             // 2048
#define DKV  (KVH * HD)            // 512
#define BS   (BB * SS)             // 4096

// ---------------- tiling ----------------
#define BM 128
#define BN 128
#define BK 32
#define BKP 40                      // padded K stride (bf16 elems) -> 80B rows
#define NTHR 256

// ---------------- device scratch ----------------
__device__ float g_qp [(size_t)BS * DOUT];
__device__ float g_kp [(size_t)BS * DKV];
__device__ float g_vp [(size_t)BS * DKV];
__device__ float g_qhm[(size_t)BS * DOUT];            // [b,nh,s,hd]
__device__ float g_khm[(size_t)BS * DKV];             // [b,kv,s,hd]
__device__ float g_vT [(size_t)BB * KVH * HD * SS];   // [b,kv,hd,s]
__device__ float g_ctx[(size_t)BS * DOUT];
__device__ float g_scores[(size_t)BB * NH * SS * SS];
__device__ float g_rowinv[(size_t)BB * NH * SS];
__device__ float g_WqT[(size_t)DOUT * DIN];
__device__ float g_WkT[(size_t)DKV  * DIN];
__device__ float g_WvT[(size_t)DKV  * DIN];
__device__ float g_WoT[(size_t)DIN  * DOUT];

// ---------------- helpers ----------------
__device__ __forceinline__ uint32_t smem_u32(const void* p) {
    uint32_t a;
    asm("{ .reg .u64 t; cvta.to.shared.u64 t, %1; cvt.u32.u64 %0, t; }"
        : "=r"(a) : "l"(p));
    return a;
}
__device__ __forceinline__ uint32_t pack_bf(__nv_bfloat16 a, __nv_bfloat16 b) {
    uint16_t ua = *reinterpret_cast<uint16_t*>(&a);
    uint16_t ub = *reinterpret_cast<uint16_t*>(&b);
    return (uint32_t)ua | ((uint32_t)ub << 16);
}
__device__ __forceinline__ void split_store(__nv_bfloat16* hi, __nv_bfloat16* lo,
                                            int r, int kq, float4 v) {
    __nv_bfloat16 h0 = __float2bfloat16(v.x), h1 = __float2bfloat16(v.y);
    __nv_bfloat16 h2 = __float2bfloat16(v.z), h3 = __float2bfloat16(v.w);
    __nv_bfloat16 l0 = __float2bfloat16(v.x - __bfloat162float(h0));
    __nv_bfloat16 l1 = __float2bfloat16(v.y - __bfloat162float(h1));
    __nv_bfloat16 l2 = __float2bfloat16(v.z - __bfloat162float(h2));
    __nv_bfloat16 l3 = __float2bfloat16(v.w - __bfloat162float(h3));
    *reinterpret_cast<uint2*>(hi + r * BKP + kq) =
        make_uint2(pack_bf(h0, h1), pack_bf(h2, h3));
    *reinterpret_cast<uint2*>(lo + r * BKP + kq) =
        make_uint2(pack_bf(l0, l1), pack_bf(l2, l3));
}
__device__ __forceinline__ void ldm4(uint32_t* d, uint32_t addr) {
    asm volatile("ldmatrix.sync.aligned.m8n8.x4.shared.b16 {%0,%1,%2,%3}, [%4];"
                 : "=r"(d[0]), "=r"(d[1]), "=r"(d[2]), "=r"(d[3]) : "r"(addr));
}
__device__ __forceinline__ void mma16816(float* c, const uint32_t* a, const uint32_t* b) {
    asm volatile(
        "mma.sync.aligned.m16n8k16.row.col.f32.bf16.bf16.f32 "
        "{%0,%1,%2,%3}, {%4,%5,%6,%7}, {%8,%9}, {%0,%1,%2,%3};"
        : "+f"(c[0]), "+f"(c[1]), "+f"(c[2]), "+f"(c[3])
        : "r"(a[0]), "r"(a[1]), "r"(a[2]), "r"(a[3]), "r"(b[0]), "r"(b[1]));
}

// ---------------- HMMA bf16x3 NT gemm core ----------------
// C[m0:m0+128, n0:n0+128] = alpha * rowscale[r] * (A[M,K] @ B[N,K]^T)
__device__ __forceinline__ void mma_core(
    const float* __restrict__ A, int lda,
    const float* __restrict__ B, int ldb,
    float* __restrict__ C, int ldc,
    int kmax, float alpha, int m0, int n0,
    bool causal, const float* __restrict__ rowscale)
{
    __shared__ __nv_bfloat16 sAhi[BM * BKP], sAlo[BM * BKP];
    __shared__ __nv_bfloat16 sBhi[BN * BKP], sBlo[BN * BKP];

    const int tid  = threadIdx.x;
    const int lane = tid & 31;
    const int wid  = tid >> 5;
    const int wm   = wid & 1;          // 2 warps along M (64 rows each)
    const int wn   = wid >> 1;         // 4 warps along N (32 cols each)

    float acc[4][4][4];
#pragma unroll
    for (int i = 0; i < 4; i++)
#pragma unroll
        for (int j = 0; j < 4; j++)
#pragma unroll
            for (int k = 0; k < 4; k++) acc[i][j][k] = 0.f;

    // ldmatrix per-thread byte offsets (A-style & B-style groupings)
    const uint32_t aoff =
        (uint32_t)(((wm * 64 + (lane & 15)) * BKP + ((lane >> 4) * 8)) * 2);
    const uint32_t boff =
        (uint32_t)(((wn * 32 + ((lane >> 4) * 8) + (lane & 7)) * BKP +
                    (((lane >> 3) & 1) * 8)) * 2);
    const uint32_t aHi = smem_u32(sAhi) + aoff;
    const uint32_t aLo = smem_u32(sAlo) + aoff;
    const uint32_t bHi = smem_u32(sBhi) + boff;
    const uint32_t bLo = smem_u32(sBlo) + boff;

    const int fr = tid >> 3;           // fill row 0..31
    const int kq = (tid & 7) * 4;      // fill k offset

    for (int k0 = 0; k0 < kmax; k0 += BK) {
        __syncthreads();
#pragma unroll
        for (int i = 0; i < 4; i++) {
            const int rr = fr + i * 32;
            float4 va = *reinterpret_cast<const float4*>(
                A + (size_t)(m0 + rr) * lda + k0 + kq);
            split_store(sAhi, sAlo, rr, kq, va);
            float4 vb = *reinterpret_cast<const float4*>(
                B + (size_t)(n0 + rr) * ldb + k0 + kq);
            split_store(sBhi, sBlo, rr, kq, vb);
        }
        __syncthreads();

#pragma unroll
        for (int ks = 0; ks < 2; ks++) {
            uint32_t bh[8], bl[8];
            ldm4(bh + 0, bHi + ks * 32);
            ldm4(bh + 4, bHi + 16 * BKP * 2 + ks * 32);
            ldm4(bl + 0, bLo + ks * 32);
            ldm4(bl + 4, bLo + 16 * BKP * 2 + ks * 32);
#pragma unroll
            for (int mt = 0; mt < 4; mt++) {
                uint32_t ah[4], al[4];
                ldm4(ah, aHi + mt * 16 * BKP * 2 + ks * 32);
                ldm4(al, aLo + mt * 16 * BKP * 2 + ks * 32);
#pragma unroll
                for (int nt = 0; nt < 4; nt++) {
                    mma16816(acc[mt][nt], ah, &bh[nt * 2]);   // hi*hi
                    mma16816(acc[mt][nt], al, &bh[nt * 2]);   // lo*hi
                    mma16816(acc[mt][nt], ah, &bl[nt * 2]);   // hi*lo
                }
            }
        }
    }

    // ---- epilogue ----
#pragma unroll
    for (int mt = 0; mt < 4; mt++) {
#pragma unroll
        for (int half = 0; half < 2; half++) {
            const int row = m0 + wm * 64 + mt * 16 + (lane >> 2) + half * 8;
            const float rs = (rowscale ? rowscale[row] : 1.0f) * alpha;
            float* cr = C + (size_t)row * ldc;
#pragma unroll
            for (int nt = 0; nt < 4; nt++) {
                const int col = n0 + wn * 32 + nt * 8 + (lane & 3) * 2;
                float2 v;
                v.x = acc[mt][nt][half * 2 + 0] * rs;
                v.y = acc[mt][nt][half * 2 + 1] * rs;
                if (causal) {
                    if (col > row)     v.x = 0.f;
                    if (col + 1 > row) v.y = 0.f;
                }
                *reinterpret_cast<float2*>(cr + col) = v;
            }
        }
    }
}

// ---------------- gemm wrapper kernels ----------------
__global__ void __launch_bounds__(NTHR, 2)
k_mma_dense(const float* __restrict__ A, int lda,
            const float* __restrict__ B, int ldb,
            float* __restrict__ C, int ldc, int K)
{
    mma_core(A, lda, B, ldb, C, ldc, K, 1.0f,
             blockIdx.y * BM, blockIdx.x * BN, false, nullptr);
}

__global__ void __launch_bounds__(NTHR, 2)
k_mma_scores(const float* __restrict__ qhm, const float* __restrict__ khm,
             float* __restrict__ scores)
{
    const int m0 = blockIdx.y * BM;
    const int n0 = blockIdx.x * BN;
    if (n0 > m0) return;                   // fully-masked tile
    const int bh  = blockIdx.z;
    const int b   = bh / NH;
    const int kvh = (bh % NH) / GRP;
    mma_core(qhm + (size_t)bh * SS * HD, HD,
             khm + (size_t)(b * KVH + kvh) * SS * HD, HD,
             scores + (size_t)bh * SS * SS, SS,
             HD, 0.08838834764831845f, m0, n0, n0 == m0, nullptr);
}

__global__ void __launch_bounds__(NTHR, 2)
k_mma_pv(const float* __restrict__ scores, const float* __restrict__ vT,
         const float* __restrict__ rowinv, float* __restrict__ ctx)
{
    const int bh  = blockIdx.z;
    const int b   = bh / NH;
    const int h   = bh % NH;
    const int kvh = h / GRP;
    const int m0  = blockIdx.y * BM;
    mma_core(scores + (size_t)bh * SS * SS, SS,
             vT + (size_t)(b * KVH + kvh) * HD * SS, SS,
             ctx + (size_t)b * SS * DOUT + h * HD, DOUT,
             m0 + BM, 1.0f, m0, 0, false,
             rowinv + (size_t)bh * SS);
}

// ---------------- transpose kernels ----------------
__global__ void k_transpose(const float* __restrict__ in, int ldin,
                            float* __restrict__ out, int ldout)
{
    __shared__ float t[32][33];
    const int c0 = blockIdx.x * 32, r0 = blockIdx.y * 32;
    const int tx = threadIdx.x, ty = threadIdx.y;   // 32 x 8
#pragma unroll
    for (int i = 0; i < 32; i += 8)
        t[ty + i][tx] = in[(size_t)(r0 + ty + i) * ldin + c0 + tx];
    __syncthreads();
#pragma unroll
    for (int i = 0; i < 32; i += 8)
        out[(size_t)(c0 + ty + i) * ldout + r0 + tx] = t[tx][ty + i];
}

__global__ void k_vtrans(const float* __restrict__ vp, float* __restrict__ vT)
{
    __shared__ float t[32][33];
    const int z = blockIdx.z;                 // b*KVH + kv
    const int b = z / KVH, kv = z % KVH;
    const float* ip = vp + (size_t)b * SS * DKV + kv * HD;
    float* op = vT + (size_t)z * HD * SS;
    const int c0 = blockIdx.x * 32, r0 = blockIdx.y * 32;
    const int tx = threadIdx.x, ty = threadIdx.y;
#pragma unroll
    for (int i = 0; i < 32; i += 8)
        t[ty + i][tx] = ip[(size_t)(r0 + ty + i) * DKV + c0 + tx];
    __syncthreads();
#pragma unroll
    for (int i = 0; i < 32; i += 8)
        op[(size_t)(c0 + ty + i) * SS + r0 + tx] = t[tx][ty + i];
}

// ---------------- rmsnorm + rope + head-major transpose ----------------
__global__ void k_normrope(const float* __restrict__ in,
                           float* __restrict__ out,
                           const float* __restrict__ cosb,
                           const float* __restrict__ sinb,
                           const float* __restrict__ scale,
                           int nheads)
{
    const int idx = blockIdx.x;
    const int h   = idx % nheads;
    const int bs  = idx / nheads;
    const int b   = bs / SS;
    const int pos = bs % SS;
    const int d   = threadIdx.x;

    float x = in[(size_t)bs * (nheads * HD) + h * HD + d];

    __shared__ float red[4];
    float v = x * x;
#pragma unroll
    for (int o = 16; o; o >>= 1) v += __shfl_xor_sync(0xffffffffu, v, o);
    if ((d & 31) == 0) red[d >> 5] = v;
    __syncthreads();
    const float ms = (red[0] + red[1] + red[2] + red[3]) * (1.0f / HD);
    const float xn = x * rsqrtf(ms + 1e-6f) * scale[d];

    __shared__ float sh[HD];
    sh[d] = xn;
    __syncthreads();
    const float rot = (d < HD / 2) ? -sh[d + HD / 2] : sh[d - HD / 2];
    const float o = xn * cosb[pos * HD + d] + rot * sinb[pos * HD + d];
    out[((size_t)(b * nheads + h) * SS + pos) * HD + d] = o;
}

// ---------------- softmax: store unnormalized exp + 1/sum ----------------
__global__ void k_softmax(float* __restrict__ scores, float* __restrict__ rowinv)
{
    const int i  = blockIdx.x;
    const int bh = blockIdx.y;
    float* row = scores + ((size_t)bh * SS + i) * SS;
    const int n = i + 1;
    const int tid = threadIdx.x;

    __shared__ float red[8];

    float m = -3.4e38f;
    for (int j = tid; j < n; j += NTHR) m = fmaxf(m, row[j]);
#pragma unroll
    for (int o = 16; o; o >>= 1) m = fmaxf(m, __shfl_xor_sync(0xffffffffu, m, o));
    if ((tid & 31) == 0) red[tid >> 5] = m;
    __syncthreads();
    float mm = red[0];
#pragma unroll
    for (int r2 = 1; r2 < 8; r2++) mm = fmaxf(mm, red[r2]);
    __syncthreads();

    float ssum = 0.f;
    for (int j = tid; j < n; j += NTHR) {
        const float e = __expf(row[j] - mm);
        row[j] = e;
        ssum += e;
    }
#pragma unroll
    for (int o = 16; o; o >>= 1) ssum += __shfl_xor_sync(0xffffffffu, ssum, o);
    if ((tid & 31) == 0) red[tid >> 5] = ssum;
    __syncthreads();
    if (tid == 0) {
        float tot = 0.f;
#pragma unroll
        for (int r2 = 0; r2 < 8; r2++) tot += red[r2];
        rowinv[(size_t)bh * SS + i] = 1.0f / tot;
    }
}

// ---------------- launch ----------------
extern "C" void kernel_launch(void* const* d_in, const int* in_sizes, int n_in,
                              void* d_out, int out_size)
{
    const float* x    = (const float*)d_in[0];
    const float* cosb = (const float*)d_in[2];
    const float* sinb = (const float*)d_in[3];
    const float* Wq   = (const float*)d_in[4];
    const float* Wk   = (const float*)d_in[5];
    const float* Wv   = (const float*)d_in[6];
    const float* Wo   = (const float*)d_in[7];
    const float* qs   = (const float*)d_in[8];
    const float* ks   = (const float*)d_in[9];
    float* out = (float*)d_out;

    float *qp, *kp, *vp, *qhm, *khm, *vT, *ctx, *sc, *rinv;
    float *WqT, *WkT, *WvT, *WoT;
    cudaGetSymbolAddress((void**)&qp,  g_qp);
    cudaGetSymbolAddress((void**)&kp,  g_kp);
    cudaGetSymbolAddress((void**)&vp,  g_vp);
    cudaGetSymbolAddress((void**)&qhm, g_qhm);
    cudaGetSymbolAddress((void**)&khm, g_khm);
    cudaGetSymbolAddress((void**)&vT,  g_vT);
    cudaGetSymbolAddress((void**)&ctx, g_ctx);
    cudaGetSymbolAddress((void**)&sc,  g_scores);
    cudaGetSymbolAddress((void**)&rinv, g_rowinv);
    cudaGetSymbolAddress((void**)&WqT, g_WqT);
    cudaGetSymbolAddress((void**)&WkT, g_WkT);
    cudaGetSymbolAddress((void**)&WvT, g_WvT);
    cudaGetSymbolAddress((void**)&WoT, g_WoT);

    const dim3 tb(32, 8);

    // Weight transposes: W[K,N] -> WT[N,K]
    k_transpose<<<dim3(DOUT / 32, DIN / 32), tb>>>(Wq, DOUT, WqT, DIN);
    k_transpose<<<dim3(DKV  / 32, DIN / 32), tb>>>(Wk, DKV,  WkT, DIN);
    k_transpose<<<dim3(DKV  / 32, DIN / 32), tb>>>(Wv, DKV,  WvT, DIN);
    k_transpose<<<dim3(DIN / 32, DOUT / 32), tb>>>(Wo, DIN,  WoT, DOUT);

    // Projections (NT: A[M,K] @ WT[N,K]^T)
    k_mma_dense<<<dim3(DOUT / BN, BS / BM), NTHR>>>(x, DIN, WqT, DIN, qp, DOUT, DIN);
    k_mma_dense<<<dim3(DKV  / BN, BS / BM), NTHR>>>(x, DIN, WkT, DIN, kp, DKV,  DIN);
    k_mma_dense<<<dim3(DKV  / BN, BS / BM), NTHR>>>(x, DIN, WvT, DIN, vp, DKV,  DIN);

    // RMSNorm + RoPE + head-major
    k_normrope<<<BS * NH,  HD>>>(qp, qhm, cosb, sinb, qs, NH);
    k_normrope<<<BS * KVH, HD>>>(kp, khm, cosb, sinb, ks, KVH);

    // V transpose per head: [s, hd] -> [hd, s]
    k_vtrans<<<dim3(HD / 32, SS / 32, BB * KVH), tb>>>(vp, vT);

    // Attention
    k_mma_scores<<<dim3(SS / BN, SS / BM, BB * NH), NTHR>>>(qhm, khm, sc);
    k_softmax<<<dim3(SS, BB * NH), NTHR>>>(sc, rinv);
    k_mma_pv<<<dim3(1, SS / BM, BB * NH), NTHR>>>(sc, vT, rinv, ctx);

    // Output projection
    k_mma_dense<<<dim3(DIN / BN, BS / BM), NTHR>>>(ctx, DOUT, WoT, DOUT, out, DIN, DOUT);
}

// round 7
// speedup vs baseline: 2.6067x; 1.1368x over previous
#include <cuda_runtime.h>
#include <cuda_bf16.h>
#include <stdint.h>
#include <math.h>

// ---------------- problem constants ----------------
#define BB   2
#define SS   2048
#define DIN  2048
#define NH   16
#define KVH  4
#define HD   128
#define GRP  (NH / KVH)            // 4
#define DOUT (NH * HD)             // 2048
#define DKV  (KVH * HD)            // 512
#define BS   (BB * SS)             // 4096

// ---------------- tiling ----------------
#define BM 128
#define BN 128
#define BK 32
#define BKP 40                      // padded K stride (bf16 elems) -> 80B rows
#define NTHR 256

#define OFF_AHI 0
#define OFF_ALO (BM * BKP * 2)
#define OFF_BHI (2 * BM * BKP * 2)
#define OFF_BLO (3 * BM * BKP * 2)
#define STAGE   (4 * BM * BKP * 2)      // 40960 B
#define SMEM_DYN (2 * STAGE)            // 81920 B

typedef __nv_bfloat16 bf;

// ---------------- device scratch ----------------
__device__ float g_qp [(size_t)BS * DOUT];
__device__ float g_kp [(size_t)BS * DKV];
__device__ float g_vp [(size_t)BS * DKV];
__device__ float g_scores[(size_t)BB * NH * SS * SS];
__device__ float g_rowinv[(size_t)BB * NH * SS];

__device__ bf g_xh [(size_t)BS * DIN],  g_xl [(size_t)BS * DIN];
__device__ bf g_WqTh[(size_t)DOUT * DIN], g_WqTl[(size_t)DOUT * DIN];
__device__ bf g_WkTh[(size_t)DKV  * DIN], g_WkTl[(size_t)DKV  * DIN];
__device__ bf g_WvTh[(size_t)DKV  * DIN], g_WvTl[(size_t)DKV  * DIN];
__device__ bf g_WoTh[(size_t)DIN * DOUT], g_WoTl[(size_t)DIN * DOUT];
__device__ bf g_qhmh[(size_t)BS * DOUT],  g_qhml[(size_t)BS * DOUT];
__device__ bf g_khmh[(size_t)BS * DKV],   g_khml[(size_t)BS * DKV];
__device__ bf g_vTh [(size_t)BB * KVH * HD * SS], g_vTl[(size_t)BB * KVH * HD * SS];
__device__ bf g_Ph  [(size_t)BB * NH * SS * SS],  g_Pl [(size_t)BB * NH * SS * SS];
__device__ bf g_ctxh[(size_t)BS * DOUT],  g_ctxl[(size_t)BS * DOUT];

// ---------------- helpers ----------------
__device__ __forceinline__ uint32_t smem_u32(const void* p) {
    uint32_t a;
    asm("{ .reg .u64 t; cvta.to.shared.u64 t, %1; cvt.u32.u64 %0, t; }"
        : "=r"(a) : "l"(p));
    return a;
}
__device__ __forceinline__ uint32_t pack_bf(bf a, bf b) {
    uint16_t ua = *reinterpret_cast<uint16_t*>(&a);
    uint16_t ub = *reinterpret_cast<uint16_t*>(&b);
    return (uint32_t)ua | ((uint32_t)ub << 16);
}
__device__ __forceinline__ void split2(float x, float y, bf* hi, bf* lo,
                                       uint32_t idx) {
    bf h0 = __float2bfloat16(x), h1 = __float2bfloat16(y);
    bf l0 = __float2bfloat16(x - __bfloat162float(h0));
    bf l1 = __float2bfloat16(y - __bfloat162float(h1));
    *reinterpret_cast<uint32_t*>(hi + idx) = pack_bf(h0, h1);
    *reinterpret_cast<uint32_t*>(lo + idx) = pack_bf(l0, l1);
}
__device__ __forceinline__ void cpasync16(uint32_t dst, const void* src) {
    asm volatile("cp.async.cg.shared.global [%0], [%1], 16;"
                 :: "r"(dst), "l"(src));
}
__device__ __forceinline__ void ldm4(uint32_t* d, uint32_t addr) {
    asm volatile("ldmatrix.sync.aligned.m8n8.x4.shared.b16 {%0,%1,%2,%3}, [%4];"
                 : "=r"(d[0]), "=r"(d[1]), "=r"(d[2]), "=r"(d[3]) : "r"(addr));
}
__device__ __forceinline__ void mma16816(float* c, const uint32_t* a, const uint32_t* b) {
    asm volatile(
        "mma.sync.aligned.m16n8k16.row.col.f32.bf16.bf16.f32 "
        "{%0,%1,%2,%3}, {%4,%5,%6,%7}, {%8,%9}, {%0,%1,%2,%3};"
        : "+f"(c[0]), "+f"(c[1]), "+f"(c[2]), "+f"(c[3])
        : "r"(a[0]), "r"(a[1]), "r"(a[2]), "r"(a[3]), "r"(b[0]), "r"(b[1]));
}

// ---------------- pipelined HMMA bf16x3 NT gemm core ----------------
// Out = alpha * rowscale[r] * (A[M,K] @ B[N,K]^T); A/B pre-split bf16 hi/lo.
// SPLIT_OUT: write Chi/Clo bf16 split; else write Cf fp32 (optional causal zero).
template <bool SPLIT_OUT>
__device__ __forceinline__ void mma_core(
    char* dyn,
    const bf* __restrict__ Ahi, const bf* __restrict__ Alo, int lda,
    const bf* __restrict__ Bhi, const bf* __restrict__ Blo, int ldb,
    float* __restrict__ Cf, bf* __restrict__ Chi, bf* __restrict__ Clo, int ldc,
    int kmax, float alpha, int m0, int n0,
    bool causal, const float* __restrict__ rowscale)
{
    const int tid  = threadIdx.x;
    const int lane = tid & 31;
    const int wid  = tid >> 5;
    const int wm   = wid & 1;          // 2 warps along M (64 rows)
    const int wn   = wid >> 1;         // 4 warps along N (32 cols)
    const uint32_t sb = smem_u32(dyn);

    float acc[4][4][4];
#pragma unroll
    for (int i = 0; i < 4; i++)
#pragma unroll
        for (int j = 0; j < 4; j++)
#pragma unroll
            for (int k = 0; k < 4; k++) acc[i][j][k] = 0.f;

    const uint32_t aoff =
        (uint32_t)(((wm * 64 + (lane & 15)) * BKP + ((lane >> 4) * 8)) * 2);
    const uint32_t boff =
        (uint32_t)(((wn * 32 + ((lane >> 4) * 8) + (lane & 7)) * BKP +
                    (((lane >> 3) & 1) * 8)) * 2);

    // fill mapping: 2 iterations x 4 arrays x 16B per thread
    const int frow = tid >> 2;
    const int fkg  = (tid & 3) * 8;

    const int nch = kmax / BK;

    // prologue: stage 0
#pragma unroll
    for (int i = 0; i < 2; i++) {
        const int row = frow + i * 64;
        const uint32_t so = (uint32_t)(row * BKP + fkg) * 2;
        const size_t ai = (size_t)(m0 + row) * lda + fkg;
        const size_t bi = (size_t)(n0 + row) * ldb + fkg;
        cpasync16(sb + OFF_AHI + so, Ahi + ai);
        cpasync16(sb + OFF_ALO + so, Alo + ai);
        cpasync16(sb + OFF_BHI + so, Bhi + bi);
        cpasync16(sb + OFF_BLO + so, Blo + bi);
    }
    asm volatile("cp.async.commit_group;");

    for (int ch = 0; ch < nch; ch++) {
        const uint32_t base = sb + (uint32_t)(ch & 1) * STAGE;
        if (ch + 1 < nch) {
            const uint32_t nb = sb + (uint32_t)((ch + 1) & 1) * STAGE;
            const int k0 = (ch + 1) * BK;
#pragma unroll
            for (int i = 0; i < 2; i++) {
                const int row = frow + i * 64;
                const uint32_t so = (uint32_t)(row * BKP + fkg) * 2;
                const size_t ai = (size_t)(m0 + row) * lda + k0 + fkg;
                const size_t bi = (size_t)(n0 + row) * ldb + k0 + fkg;
                cpasync16(nb + OFF_AHI + so, Ahi + ai);
                cpasync16(nb + OFF_ALO + so, Alo + ai);
                cpasync16(nb + OFF_BHI + so, Bhi + bi);
                cpasync16(nb + OFF_BLO + so, Blo + bi);
            }
            asm volatile("cp.async.commit_group;");
            asm volatile("cp.async.wait_group 1;");
        } else {
            asm volatile("cp.async.wait_group 0;");
        }
        __syncthreads();

        const uint32_t aHi = base + OFF_AHI + aoff;
        const uint32_t aLo = base + OFF_ALO + aoff;
        const uint32_t bHi = base + OFF_BHI + boff;
        const uint32_t bLo = base + OFF_BLO + boff;
#pragma unroll
        for (int ks = 0; ks < 2; ks++) {
            uint32_t bh[8], bl[8];
            ldm4(bh + 0, bHi + ks * 32);
            ldm4(bh + 4, bHi + 16 * BKP * 2 + ks * 32);
            ldm4(bl + 0, bLo + ks * 32);
            ldm4(bl + 4, bLo + 16 * BKP * 2 + ks * 32);
#pragma unroll
            for (int mt = 0; mt < 4; mt++) {
                uint32_t ah[4], al[4];
                ldm4(ah, aHi + mt * 16 * BKP * 2 + ks * 32);
                ldm4(al, aLo + mt * 16 * BKP * 2 + ks * 32);
#pragma unroll
                for (int nt = 0; nt < 4; nt++) {
                    mma16816(acc[mt][nt], ah, &bh[nt * 2]);   // hi*hi
                    mma16816(acc[mt][nt], al, &bh[nt * 2]);   // lo*hi
                    mma16816(acc[mt][nt], ah, &bl[nt * 2]);   // hi*lo
                }
            }
        }
        __syncthreads();
    }

    // ---- epilogue ----
#pragma unroll
    for (int mt = 0; mt < 4; mt++) {
#pragma unroll
        for (int half = 0; half < 2; half++) {
            const int row = m0 + wm * 64 + mt * 16 + (lane >> 2) + half * 8;
            const float rs = (rowscale ? rowscale[row] : 1.0f) * alpha;
#pragma unroll
            for (int nt = 0; nt < 4; nt++) {
                const int col = n0 + wn * 32 + nt * 8 + (lane & 3) * 2;
                float vx = acc[mt][nt][half * 2 + 0] * rs;
                float vy = acc[mt][nt][half * 2 + 1] * rs;
                if (SPLIT_OUT) {
                    split2(vx, vy, Chi, Clo, (uint32_t)((size_t)row * ldc + col));
                } else {
                    if (causal) {
                        if (col > row)     vx = 0.f;
                        if (col + 1 > row) vy = 0.f;
                    }
                    *reinterpret_cast<float2*>(Cf + (size_t)row * ldc + col) =
                        make_float2(vx, vy);
                }
            }
        }
    }
}

// ---------------- gemm wrapper kernels ----------------
__global__ void __launch_bounds__(NTHR)
k_mma_dense(const bf* __restrict__ Ahi, const bf* __restrict__ Alo, int lda,
            const bf* __restrict__ Bhi, const bf* __restrict__ Blo, int ldb,
            float* __restrict__ C, int ldc, int K)
{
    extern __shared__ char dyn[];
    mma_core<false>(dyn, Ahi, Alo, lda, Bhi, Blo, ldb, C, nullptr, nullptr, ldc,
                    K, 1.0f, blockIdx.y * BM, blockIdx.x * BN, false, nullptr);
}

__global__ void __launch_bounds__(NTHR)
k_mma_scores(const bf* __restrict__ qh, const bf* __restrict__ ql,
             const bf* __restrict__ kh, const bf* __restrict__ kl,
             float* __restrict__ scores)
{
    const int m0 = blockIdx.y * BM;
    const int n0 = blockIdx.x * BN;
    if (n0 > m0) return;
    const int bh  = blockIdx.z;
    const int b   = bh / NH;
    const int kvh = (bh % NH) / GRP;
    const size_t qo = (size_t)bh * SS * HD;
    const size_t ko = (size_t)(b * KVH + kvh) * SS * HD;
    extern __shared__ char dyn[];
    mma_core<false>(dyn, qh + qo, ql + qo, HD, kh + ko, kl + ko, HD,
                    scores + (size_t)bh * SS * SS, nullptr, nullptr, SS,
                    HD, 0.08838834764831845f, m0, n0, n0 == m0, nullptr);
}

__global__ void __launch_bounds__(NTHR)
k_mma_pv(const bf* __restrict__ Ph, const bf* __restrict__ Pl,
         const bf* __restrict__ vh, const bf* __restrict__ vl,
         const float* __restrict__ rowinv,
         bf* __restrict__ ctxh, bf* __restrict__ ctxl)
{
    const int bh  = blockIdx.z;
    const int b   = bh / NH;
    const int h   = bh % NH;
    const int kvh = h / GRP;
    const int m0  = blockIdx.y * BM;
    const size_t po = (size_t)bh * SS * SS;
    const size_t vo = (size_t)(b * KVH + kvh) * HD * SS;
    const size_t co = (size_t)b * SS * DOUT + h * HD;
    extern __shared__ char dyn[];
    mma_core<true>(dyn, Ph + po, Pl + po, SS, vh + vo, vl + vo, SS,
                   nullptr, ctxh + co, ctxl + co, DOUT,
                   m0 + BM, 1.0f, m0, 0, false, rowinv + (size_t)bh * SS);
}

// ---------------- prep kernels ----------------
__global__ void k_split(const float* __restrict__ in, bf* __restrict__ hi,
                        bf* __restrict__ lo, int n)
{
    const int i = (blockIdx.x * blockDim.x + threadIdx.x) * 2;
    if (i < n) {
        float2 v = *reinterpret_cast<const float2*>(in + i);
        split2(v.x, v.y, hi, lo, (uint32_t)i);
    }
}

__global__ void k_tsplit(const float* __restrict__ in, int ldin,
                         bf* __restrict__ oh, bf* __restrict__ ol, int ldout)
{
    __shared__ float t[32][33];
    const int c0 = blockIdx.x * 32, r0 = blockIdx.y * 32;
    const int tx = threadIdx.x, ty = threadIdx.y;   // 32 x 8
#pragma unroll
    for (int i = 0; i < 32; i += 8)
        t[ty + i][tx] = in[(size_t)(r0 + ty + i) * ldin + c0 + tx];
    __syncthreads();
#pragma unroll
    for (int i = 0; i < 32; i += 8) {
        const float v = t[tx][ty + i];
        const size_t idx = (size_t)(c0 + ty + i) * ldout + r0 + tx;
        bf h = __float2bfloat16(v);
        oh[idx] = h;
        ol[idx] = __float2bfloat16(v - __bfloat162float(h));
    }
}

__global__ void k_vtrans(const float* __restrict__ vp,
                         bf* __restrict__ oh, bf* __restrict__ ol)
{
    __shared__ float t[32][33];
    const int z = blockIdx.z;
    const int b = z / KVH, kv = z % KVH;
    const float* ip = vp + (size_t)b * SS * DKV + kv * HD;
    const size_t obase = (size_t)z * HD * SS;
    const int c0 = blockIdx.x * 32, r0 = blockIdx.y * 32;
    const int tx = threadIdx.x, ty = threadIdx.y;
#pragma unroll
    for (int i = 0; i < 32; i += 8)
        t[ty + i][tx] = ip[(size_t)(r0 + ty + i) * DKV + c0 + tx];
    __syncthreads();
#pragma unroll
    for (int i = 0; i < 32; i += 8) {
        const float v = t[tx][ty + i];
        const size_t idx = obase + (size_t)(c0 + ty + i) * SS + r0 + tx;
        bf h = __float2bfloat16(v);
        oh[idx] = h;
        ol[idx] = __float2bfloat16(v - __bfloat162float(h));
    }
}

// ---------------- rmsnorm + rope + head-major + split ----------------
__global__ void k_normrope(const float* __restrict__ in,
                           bf* __restrict__ oh, bf* __restrict__ ol,
                           const float* __restrict__ cosb,
                           const float* __restrict__ sinb,
                           const float* __restrict__ scale,
                           int nheads)
{
    const int idx = blockIdx.x;
    const int h   = idx % nheads;
    const int bs  = idx / nheads;
    const int b   = bs / SS;
    const int pos = bs % SS;
    const int d   = threadIdx.x;

    float x = in[(size_t)bs * (nheads * HD) + h * HD + d];

    __shared__ float red[4];
    float v = x * x;
#pragma unroll
    for (int o = 16; o; o >>= 1) v += __shfl_xor_sync(0xffffffffu, v, o);
    if ((d & 31) == 0) red[d >> 5] = v;
    __syncthreads();
    const float ms = (red[0] + red[1] + red[2] + red[3]) * (1.0f / HD);
    const float xn = x * rsqrtf(ms + 1e-6f) * scale[d];

    __shared__ float sh[HD];
    sh[d] = xn;
    __syncthreads();
    const float rot = (d < HD / 2) ? -sh[d + HD / 2] : sh[d - HD / 2];
    const float o = xn * cosb[pos * HD + d] + rot * sinb[pos * HD + d];
    const size_t oidx = ((size_t)(b * nheads + h) * SS + pos) * HD + d;
    bf hh = __float2bfloat16(o);
    oh[oidx] = hh;
    ol[oidx] = __float2bfloat16(o - __bfloat162float(hh));
}

// ---------------- softmax: P = exp(s - max) split bf16, rowinv = 1/sum ----
__global__ void k_softmax(const float* __restrict__ scores,
                          bf* __restrict__ Ph, bf* __restrict__ Pl,
                          float* __restrict__ rowinv)
{
    const int i  = blockIdx.x;
    const int bh = blockIdx.y;
    const float* row = scores + ((size_t)bh * SS + i) * SS;
    bf* ph = Ph + ((size_t)bh * SS + i) * SS;
    bf* pl = Pl + ((size_t)bh * SS + i) * SS;
    const int n = i + 1;
    const int limit = ((i >> 7) + 1) << 7;   // pad to 128-tile for PV reads
    const int tid = threadIdx.x;

    __shared__ float red[8];

    float m = -3.4e38f;
    for (int j = tid; j < n; j += NTHR) m = fmaxf(m, row[j]);
#pragma unroll
    for (int o = 16; o; o >>= 1) m = fmaxf(m, __shfl_xor_sync(0xffffffffu, m, o));
    if ((tid & 31) == 0) red[tid >> 5] = m;
    __syncthreads();
    float mm = red[0];
#pragma unroll
    for (int r2 = 1; r2 < 8; r2++) mm = fmaxf(mm, red[r2]);
    __syncthreads();

    float ssum = 0.f;
    for (int j = tid; j < limit; j += NTHR) {
        const float e = (j < n) ? __expf(row[j] - mm) : 0.f;
        ssum += e;
        bf h = __float2bfloat16(e);
        ph[j] = h;
        pl[j] = __float2bfloat16(e - __bfloat162float(h));
    }
#pragma unroll
    for (int o = 16; o; o >>= 1) ssum += __shfl_xor_sync(0xffffffffu, ssum, o);
    if ((tid & 31) == 0) red[tid >> 5] = ssum;
    __syncthreads();
    if (tid == 0) {
        float tot = 0.f;
#pragma unroll
        for (int r2 = 0; r2 < 8; r2++) tot += red[r2];
        rowinv[(size_t)bh * SS + i] = 1.0f / tot;
    }
}

// ---------------- launch ----------------
extern "C" void kernel_launch(void* const* d_in, const int* in_sizes, int n_in,
                              void* d_out, int out_size)
{
    const float* x    = (const float*)d_in[0];
    const float* cosb = (const float*)d_in[2];
    const float* sinb = (const float*)d_in[3];
    const float* Wq   = (const float*)d_in[4];
    const float* Wk   = (const float*)d_in[5];
    const float* Wv   = (const float*)d_in[6];
    const float* Wo   = (const float*)d_in[7];
    const float* qs   = (const float*)d_in[8];
    const float* ks   = (const float*)d_in[9];
    float* out = (float*)d_out;

    float *qp, *kp, *vp, *sc, *rinv;
    bf *xh, *xl, *WqTh, *WqTl, *WkTh, *WkTl, *WvTh, *WvTl, *WoTh, *WoTl;
    bf *qhmh, *qhml, *khmh, *khml, *vTh, *vTl, *Ph, *Pl, *ctxh, *ctxl;
    cudaGetSymbolAddress((void**)&qp,   g_qp);
    cudaGetSymbolAddress((void**)&kp,   g_kp);
    cudaGetSymbolAddress((void**)&vp,   g_vp);
    cudaGetSymbolAddress((void**)&sc,   g_scores);
    cudaGetSymbolAddress((void**)&rinv, g_rowinv);
    cudaGetSymbolAddress((void**)&xh,   g_xh);
    cudaGetSymbolAddress((void**)&xl,   g_xl);
    cudaGetSymbolAddress((void**)&WqTh, g_WqTh);
    cudaGetSymbolAddress((void**)&WqTl, g_WqTl);
    cudaGetSymbolAddress((void**)&WkTh, g_WkTh);
    cudaGetSymbolAddress((void**)&WkTl, g_WkTl);
    cudaGetSymbolAddress((void**)&WvTh, g_WvTh);
    cudaGetSymbolAddress((void**)&WvTl, g_WvTl);
    cudaGetSymbolAddress((void**)&WoTh, g_WoTh);
    cudaGetSymbolAddress((void**)&WoTl, g_WoTl);
    cudaGetSymbolAddress((void**)&qhmh, g_qhmh);
    cudaGetSymbolAddress((void**)&qhml, g_qhml);
    cudaGetSymbolAddress((void**)&khmh, g_khmh);
    cudaGetSymbolAddress((void**)&khml, g_khml);
    cudaGetSymbolAddress((void**)&vTh,  g_vTh);
    cudaGetSymbolAddress((void**)&vTl,  g_vTl);
    cudaGetSymbolAddress((void**)&Ph,   g_Ph);
    cudaGetSymbolAddress((void**)&Pl,   g_Pl);
    cudaGetSymbolAddress((void**)&ctxh, g_ctxh);
    cudaGetSymbolAddress((void**)&ctxl, g_ctxl);

    cudaFuncSetAttribute(k_mma_dense,  cudaFuncAttributeMaxDynamicSharedMemorySize, SMEM_DYN);
    cudaFuncSetAttribute(k_mma_scores, cudaFuncAttributeMaxDynamicSharedMemorySize, SMEM_DYN);
    cudaFuncSetAttribute(k_mma_pv,     cudaFuncAttributeMaxDynamicSharedMemorySize, SMEM_DYN);

    const dim3 tb(32, 8);

    // Prep: transpose+split weights, split x
    k_tsplit<<<dim3(DOUT / 32, DIN / 32), tb>>>(Wq, DOUT, WqTh, WqTl, DIN);
    k_tsplit<<<dim3(DKV  / 32, DIN / 32), tb>>>(Wk, DKV,  WkTh, WkTl, DIN);
    k_tsplit<<<dim3(DKV  / 32, DIN / 32), tb>>>(Wv, DKV,  WvTh, WvTl, DIN);
    k_tsplit<<<dim3(DIN / 32, DOUT / 32), tb>>>(Wo, DIN,  WoTh, WoTl, DOUT);
    k_split<<<(BS * DIN / 2 + 255) / 256, 256>>>(x, xh, xl, BS * DIN);

    // Projections (NT)
    k_mma_dense<<<dim3(DOUT / BN, BS / BM), NTHR, SMEM_DYN>>>(
        xh, xl, DIN, WqTh, WqTl, DIN, qp, DOUT, DIN);
    k_mma_dense<<<dim3(DKV / BN, BS / BM), NTHR, SMEM_DYN>>>(
        xh, xl, DIN, WkTh, WkTl, DIN, kp, DKV, DIN);
    k_mma_dense<<<dim3(DKV / BN, BS / BM), NTHR, SMEM_DYN>>>(
        xh, xl, DIN, WvTh, WvTl, DIN, vp, DKV, DIN);

    // RMSNorm + RoPE + head-major + split
    k_normrope<<<BS * NH,  HD>>>(qp, qhmh, qhml, cosb, sinb, qs, NH);
    k_normrope<<<BS * KVH, HD>>>(kp, khmh, khml, cosb, sinb, ks, KVH);

    // V transpose + split
    k_vtrans<<<dim3(HD / 32, SS / 32, BB * KVH), tb>>>(vp, vTh, vTl);

    // Attention
    k_mma_scores<<<dim3(SS / BN, SS / BM, BB * NH), NTHR, SMEM_DYN>>>(
        qhmh, qhml, khmh, khml, sc);
    k_softmax<<<dim3(SS, BB * NH), NTHR>>>(sc, Ph, Pl, rinv);
    k_mma_pv<<<dim3(1, SS / BM, BB * NH), NTHR, SMEM_DYN>>>(
        Ph, Pl, vTh, vTl, rinv, ctxh, ctxl);

    // Output projection
    k_mma_dense<<<dim3(DIN / BN, BS / BM), NTHR, SMEM_DYN>>>(
        ctxh, ctxl, DOUT, WoTh, WoTl, DOUT, out, DIN, DOUT);
}

// round 8
// speedup vs baseline: 3.0350x; 1.1643x over previous
#include <cuda_runtime.h>
#include <cuda_bf16.h>
#include <stdint.h>
#include <math.h>

// ---------------- problem constants ----------------
#define BB   2
#define SS   2048
#define DIN  2048
#define NH   16
#define KVH  4
#define HD   128
#define GRP  (NH / KVH)            // 4
#define DOUT (NH * HD)             // 2048
#define DKV  (KVH * HD)            // 512
#define BS   (BB * SS)             // 4096

// ---------------- dense gemm tiling ----------------
#define BM 128
#define BN 128
#define BK 32
#define BKP 40
#define NTHR 256

#define OFF_AHI 0
#define OFF_ALO (BM * BKP * 2)
#define OFF_BHI (2 * BM * BKP * 2)
#define OFF_BLO (3 * BM * BKP * 2)
#define STAGE   (4 * BM * BKP * 2)      // 40960 B
#define SMEM_DYN (2 * STAGE)            // 81920 B

// ---------------- fused attention tiling ----------------
#define FBM 128
#define FBN 64
#define KSP 136                          // K tile row stride (elems)
#define VSP 72                           // V tile row stride (elems)
#define QSP 136
#define KTILE (64 * KSP * 2)             // 17408 B
#define VTILE (128 * VSP * 2)            // 18432 B
#define FSTAGE (2 * KTILE + 2 * VTILE)   // 71680 B
#define FSMEM (2 * FSTAGE)               // 143360 B
#define QBYTES (128 * QSP * 2)           // 34816 B (fits in one stage w/ lo)

typedef __nv_bfloat16 bf;

// ---------------- device scratch ----------------
__device__ float g_qp [(size_t)BS * DOUT];
__device__ float g_kp [(size_t)BS * DKV];
__device__ float g_vp [(size_t)BS * DKV];

__device__ bf g_xh [(size_t)BS * DIN],  g_xl [(size_t)BS * DIN];
__device__ bf g_WqTh[(size_t)DOUT * DIN], g_WqTl[(size_t)DOUT * DIN];
__device__ bf g_WkTh[(size_t)DKV  * DIN], g_WkTl[(size_t)DKV  * DIN];
__device__ bf g_WvTh[(size_t)DKV  * DIN], g_WvTl[(size_t)DKV  * DIN];
__device__ bf g_WoTh[(size_t)DIN * DOUT], g_WoTl[(size_t)DIN * DOUT];
__device__ bf g_qhmh[(size_t)BS * DOUT],  g_qhml[(size_t)BS * DOUT];
__device__ bf g_khmh[(size_t)BS * DKV],   g_khml[(size_t)BS * DKV];
__device__ bf g_vTh [(size_t)BB * KVH * HD * SS], g_vTl[(size_t)BB * KVH * HD * SS];
__device__ bf g_ctxh[(size_t)BS * DOUT],  g_ctxl[(size_t)BS * DOUT];

// ---------------- helpers ----------------
__device__ __forceinline__ uint32_t smem_u32(const void* p) {
    uint32_t a;
    asm("{ .reg .u64 t; cvta.to.shared.u64 t, %1; cvt.u32.u64 %0, t; }"
        : "=r"(a) : "l"(p));
    return a;
}
__device__ __forceinline__ uint32_t pack_bf(bf a, bf b) {
    uint16_t ua = *reinterpret_cast<uint16_t*>(&a);
    uint16_t ub = *reinterpret_cast<uint16_t*>(&b);
    return (uint32_t)ua | ((uint32_t)ub << 16);
}
__device__ __forceinline__ void split2(float x, float y, bf* hi, bf* lo,
                                       size_t idx) {
    bf h0 = __float2bfloat16(x), h1 = __float2bfloat16(y);
    bf l0 = __float2bfloat16(x - __bfloat162float(h0));
    bf l1 = __float2bfloat16(y - __bfloat162float(h1));
    *reinterpret_cast<uint32_t*>(hi + idx) = pack_bf(h0, h1);
    *reinterpret_cast<uint32_t*>(lo + idx) = pack_bf(l0, l1);
}
__device__ __forceinline__ void cpasync16(uint32_t dst, const void* src) {
    asm volatile("cp.async.cg.shared.global [%0], [%1], 16;"
                 :: "r"(dst), "l"(src));
}
__device__ __forceinline__ void ldm4(uint32_t* d, uint32_t addr) {
    asm volatile("ldmatrix.sync.aligned.m8n8.x4.shared.b16 {%0,%1,%2,%3}, [%4];"
                 : "=r"(d[0]), "=r"(d[1]), "=r"(d[2]), "=r"(d[3]) : "r"(addr));
}
__device__ __forceinline__ void mma16816(float* c, const uint32_t* a, const uint32_t* b) {
    asm volatile(
        "mma.sync.aligned.m16n8k16.row.col.f32.bf16.bf16.f32 "
        "{%0,%1,%2,%3}, {%4,%5,%6,%7}, {%8,%9}, {%0,%1,%2,%3};"
        : "+f"(c[0]), "+f"(c[1]), "+f"(c[2]), "+f"(c[3])
        : "r"(a[0]), "r"(a[1]), "r"(a[2]), "r"(a[3]), "r"(b[0]), "r"(b[1]));
}

// ---------------- pipelined HMMA bf16x3 NT dense gemm ----------------
__device__ __forceinline__ void mma_core(
    char* dyn,
    const bf* __restrict__ Ahi, const bf* __restrict__ Alo, int lda,
    const bf* __restrict__ Bhi, const bf* __restrict__ Blo, int ldb,
    float* __restrict__ Cf, int ldc, int kmax, int m0, int n0)
{
    const int tid  = threadIdx.x;
    const int lane = tid & 31;
    const int wid  = tid >> 5;
    const int wm   = wid & 1;
    const int wn   = wid >> 1;
    const uint32_t sb = smem_u32(dyn);

    float acc[4][4][4];
#pragma unroll
    for (int i = 0; i < 4; i++)
#pragma unroll
        for (int j = 0; j < 4; j++)
#pragma unroll
            for (int k = 0; k < 4; k++) acc[i][j][k] = 0.f;

    const uint32_t aoff =
        (uint32_t)(((wm * 64 + (lane & 15)) * BKP + ((lane >> 4) * 8)) * 2);
    const uint32_t boff =
        (uint32_t)(((wn * 32 + ((lane >> 4) * 8) + (lane & 7)) * BKP +
                    (((lane >> 3) & 1) * 8)) * 2);

    const int frow = tid >> 2;
    const int fkg  = (tid & 3) * 8;
    const int nch = kmax / BK;

#pragma unroll
    for (int i = 0; i < 2; i++) {
        const int row = frow + i * 64;
        const uint32_t so = (uint32_t)(row * BKP + fkg) * 2;
        const size_t ai = (size_t)(m0 + row) * lda + fkg;
        const size_t bi = (size_t)(n0 + row) * ldb + fkg;
        cpasync16(sb + OFF_AHI + so, Ahi + ai);
        cpasync16(sb + OFF_ALO + so, Alo + ai);
        cpasync16(sb + OFF_BHI + so, Bhi + bi);
        cpasync16(sb + OFF_BLO + so, Blo + bi);
    }
    asm volatile("cp.async.commit_group;");

    for (int ch = 0; ch < nch; ch++) {
        const uint32_t base = sb + (uint32_t)(ch & 1) * STAGE;
        if (ch + 1 < nch) {
            const uint32_t nb2 = sb + (uint32_t)((ch + 1) & 1) * STAGE;
            const int k0 = (ch + 1) * BK;
#pragma unroll
            for (int i = 0; i < 2; i++) {
                const int row = frow + i * 64;
                const uint32_t so = (uint32_t)(row * BKP + fkg) * 2;
                const size_t ai = (size_t)(m0 + row) * lda + k0 + fkg;
                const size_t bi = (size_t)(n0 + row) * ldb + k0 + fkg;
                cpasync16(nb2 + OFF_AHI + so, Ahi + ai);
                cpasync16(nb2 + OFF_ALO + so, Alo + ai);
                cpasync16(nb2 + OFF_BHI + so, Bhi + bi);
                cpasync16(nb2 + OFF_BLO + so, Blo + bi);
            }
            asm volatile("cp.async.commit_group;");
            asm volatile("cp.async.wait_group 1;");
        } else {
            asm volatile("cp.async.wait_group 0;");
        }
        __syncthreads();

        const uint32_t aHi = base + OFF_AHI + aoff;
        const uint32_t aLo = base + OFF_ALO + aoff;
        const uint32_t bHi = base + OFF_BHI + boff;
        const uint32_t bLo = base + OFF_BLO + boff;
#pragma unroll
        for (int ks = 0; ks < 2; ks++) {
            uint32_t bh[8], bl[8];
            ldm4(bh + 0, bHi + ks * 32);
            ldm4(bh + 4, bHi + 16 * BKP * 2 + ks * 32);
            ldm4(bl + 0, bLo + ks * 32);
            ldm4(bl + 4, bLo + 16 * BKP * 2 + ks * 32);
#pragma unroll
            for (int mt = 0; mt < 4; mt++) {
                uint32_t ah[4], al[4];
                ldm4(ah, aHi + mt * 16 * BKP * 2 + ks * 32);
                ldm4(al, aLo + mt * 16 * BKP * 2 + ks * 32);
#pragma unroll
                for (int nt = 0; nt < 4; nt++) {
                    mma16816(acc[mt][nt], ah, &bh[nt * 2]);
                    mma16816(acc[mt][nt], al, &bh[nt * 2]);
                    mma16816(acc[mt][nt], ah, &bl[nt * 2]);
                }
            }
        }
        __syncthreads();
    }

#pragma unroll
    for (int mt = 0; mt < 4; mt++) {
#pragma unroll
        for (int half = 0; half < 2; half++) {
            const int row = m0 + wm * 64 + mt * 16 + (lane >> 2) + half * 8;
#pragma unroll
            for (int nt = 0; nt < 4; nt++) {
                const int col = n0 + wn * 32 + nt * 8 + (lane & 3) * 2;
                *reinterpret_cast<float2*>(Cf + (size_t)row * ldc + col) =
                    make_float2(acc[mt][nt][half * 2 + 0],
                                acc[mt][nt][half * 2 + 1]);
            }
        }
    }
}

__global__ void __launch_bounds__(NTHR)
k_mma_dense(const bf* __restrict__ Ahi, const bf* __restrict__ Alo, int lda,
            const bf* __restrict__ Bhi, const bf* __restrict__ Blo, int ldb,
            float* __restrict__ C, int ldc, int K)
{
    extern __shared__ char dyn[];
    mma_core(dyn, Ahi, Alo, lda, Bhi, Blo, ldb, C, ldc, K,
             blockIdx.y * BM, blockIdx.x * BN);
}

// ---------------- fused flash attention (bf16x3 HMMA) ----------------
__global__ void __launch_bounds__(256, 1)
k_attn(const bf* __restrict__ qhp, const bf* __restrict__ qlp,
       const bf* __restrict__ khp, const bf* __restrict__ klp,
       const bf* __restrict__ vhp, const bf* __restrict__ vlp,
       bf* __restrict__ ctxh, bf* __restrict__ ctxl)
{
    extern __shared__ char dyn[];
    const uint32_t sb = smem_u32(dyn);
    const int tid = threadIdx.x, lane = tid & 31, w = tid >> 5;
    const int bh = blockIdx.y, b = bh / NH, h = bh % NH;
    const int kvh = (bh % NH) / GRP;
    const int m0 = ((int)gridDim.x - 1 - (int)blockIdx.x) * FBM;
    const size_t qo = (size_t)bh * SS * HD;
    const size_t ko = (size_t)(b * KVH + kvh) * SS * HD;
    const size_t vo = (size_t)(b * KVH + kvh) * HD * SS;

    // ---- stage Q (hi/lo) through smem, ldmatrix into registers ----
#pragma unroll
    for (int it = 0; it < 8; it++) {
        const int c = tid + it * 256;            // 2048 chunks
        const int row = c >> 4, col = (c & 15) * 8;
        const size_t gi = qo + (size_t)(m0 + row) * HD + col;
        cpasync16(sb + (uint32_t)(row * QSP + col) * 2, qhp + gi);
        cpasync16(sb + QBYTES + (uint32_t)(row * QSP + col) * 2, qlp + gi);
    }
    asm volatile("cp.async.commit_group;");
    asm volatile("cp.async.wait_group 0;");
    __syncthreads();

    uint32_t qfh[8][4], qfl[8][4];
    {
        const uint32_t ab = sb +
            (uint32_t)(((w * 16 + (lane & 15)) * QSP + (lane >> 4) * 8) * 2);
#pragma unroll
        for (int kk = 0; kk < 8; kk++) {
            ldm4(qfh[kk], ab + kk * 32);
            ldm4(qfl[kk], ab + QBYTES + kk * 32);
        }
    }
    __syncthreads();

    const int nb = m0 / FBN + 2;

    auto load_kv = [&](int i) {
        if (i < nb) {
            const int n0 = i * FBN;
            const uint32_t bufb = sb + (uint32_t)(i & 1) * FSTAGE;
#pragma unroll
            for (int it = 0; it < 4; it++) {
                const int c = tid + it * 256;        // 1024 chunks each
                const int krow = c >> 4, kcol = (c & 15) * 8;
                const size_t gk = ko + (size_t)(n0 + krow) * HD + kcol;
                cpasync16(bufb + (uint32_t)(krow * KSP + kcol) * 2, khp + gk);
                cpasync16(bufb + KTILE + (uint32_t)(krow * KSP + kcol) * 2, klp + gk);
                const int vrow = c >> 3, vcol = (c & 7) * 8;
                const size_t gv = vo + (size_t)vrow * SS + n0 + vcol;
                cpasync16(bufb + 2 * KTILE + (uint32_t)(vrow * VSP + vcol) * 2, vhp + gv);
                cpasync16(bufb + 2 * KTILE + VTILE + (uint32_t)(vrow * VSP + vcol) * 2, vlp + gv);
            }
        }
        asm volatile("cp.async.commit_group;");
    };

    load_kv(0);
    load_kv(1);

    float ctxa[16][4];
#pragma unroll
    for (int j = 0; j < 16; j++)
#pragma unroll
        for (int e = 0; e < 4; e++) ctxa[j][e] = 0.f;
    float mrow0 = -1e30f, mrow8 = -1e30f, lrow0 = 0.f, lrow8 = 0.f;

    const uint32_t kboff =
        (uint32_t)((((lane >> 4) * 8 + (lane & 7)) * KSP + ((lane >> 3) & 1) * 8) * 2);
    const uint32_t vboff =
        (uint32_t)((((lane >> 4) * 8 + (lane & 7)) * VSP + ((lane >> 3) & 1) * 8) * 2);
    const int r0g = m0 + w * 16 + (lane >> 2);
    const int cquad = 2 * (lane & 3);

    for (int i = 0; i < nb; i++) {
        asm volatile("cp.async.wait_group 1;");
        __syncthreads();
        const uint32_t base = sb + (uint32_t)(i & 1) * FSTAGE;
        const int n0 = i * FBN;

        // ---- scores: s[m16][n64] = q . k^T (3-term) ----
        float s[8][4];
#pragma unroll
        for (int j = 0; j < 8; j++)
#pragma unroll
            for (int e = 0; e < 4; e++) s[j][e] = 0.f;

        const uint32_t kb = base + kboff;
#pragma unroll
        for (int kk = 0; kk < 8; kk++) {
#pragma unroll
            for (int ng = 0; ng < 4; ng++) {
                uint32_t bh4[4], bl4[4];
                const uint32_t a = kb + (uint32_t)(ng * 16 * KSP * 2) + kk * 32;
                ldm4(bh4, a);
                ldm4(bl4, a + KTILE);
                mma16816(s[2 * ng + 0], qfh[kk], bh4 + 0);
                mma16816(s[2 * ng + 0], qfl[kk], bh4 + 0);
                mma16816(s[2 * ng + 0], qfh[kk], bl4 + 0);
                mma16816(s[2 * ng + 1], qfh[kk], bh4 + 2);
                mma16816(s[2 * ng + 1], qfl[kk], bh4 + 2);
                mma16816(s[2 * ng + 1], qfh[kk], bl4 + 2);
            }
        }

        // ---- causal mask (only diagonal-overlapping blocks) ----
        if (n0 + FBN - 1 > m0) {
#pragma unroll
            for (int j = 0; j < 8; j++) {
                const int col = n0 + j * 8 + cquad;
                if (col > r0g)         s[j][0] = -1e30f;
                if (col + 1 > r0g)     s[j][1] = -1e30f;
                if (col > r0g + 8)     s[j][2] = -1e30f;
                if (col + 1 > r0g + 8) s[j][3] = -1e30f;
            }
        }

        // ---- online softmax update ----
        float mx0 = -1e30f, mx8 = -1e30f;
#pragma unroll
        for (int j = 0; j < 8; j++) {
            mx0 = fmaxf(mx0, fmaxf(s[j][0], s[j][1]));
            mx8 = fmaxf(mx8, fmaxf(s[j][2], s[j][3]));
        }
        mx0 = fmaxf(mx0, __shfl_xor_sync(0xffffffffu, mx0, 1));
        mx0 = fmaxf(mx0, __shfl_xor_sync(0xffffffffu, mx0, 2));
        mx8 = fmaxf(mx8, __shfl_xor_sync(0xffffffffu, mx8, 1));
        mx8 = fmaxf(mx8, __shfl_xor_sync(0xffffffffu, mx8, 2));

        const float mn0 = fmaxf(mrow0, mx0), mn8 = fmaxf(mrow8, mx8);
        const float sc0 = __expf(mrow0 - mn0), sc8 = __expf(mrow8 - mn8);
        mrow0 = mn0; mrow8 = mn8;

        float sum0 = 0.f, sum8 = 0.f;
        uint32_t ph[4][4], pl[4][4];
#pragma unroll
        for (int g = 0; g < 4; g++) {
#pragma unroll
            for (int jj = 0; jj < 2; jj++) {
                const int j = 2 * g + jj;
                const float e0 = __expf(s[j][0] - mn0);
                const float e1 = __expf(s[j][1] - mn0);
                const float e2 = __expf(s[j][2] - mn8);
                const float e3 = __expf(s[j][3] - mn8);
                sum0 += e0 + e1; sum8 += e2 + e3;
                bf h0 = __float2bfloat16(e0), h1 = __float2bfloat16(e1);
                bf h2 = __float2bfloat16(e2), h3 = __float2bfloat16(e3);
                ph[g][2 * jj + 0] = pack_bf(h0, h1);
                ph[g][2 * jj + 1] = pack_bf(h2, h3);
                pl[g][2 * jj + 0] = pack_bf(
                    __float2bfloat16(e0 - __bfloat162float(h0)),
                    __float2bfloat16(e1 - __bfloat162float(h1)));
                pl[g][2 * jj + 1] = pack_bf(
                    __float2bfloat16(e2 - __bfloat162float(h2)),
                    __float2bfloat16(e3 - __bfloat162float(h3)));
            }
        }
        sum0 += __shfl_xor_sync(0xffffffffu, sum0, 1);
        sum0 += __shfl_xor_sync(0xffffffffu, sum0, 2);
        sum8 += __shfl_xor_sync(0xffffffffu, sum8, 1);
        sum8 += __shfl_xor_sync(0xffffffffu, sum8, 2);
        lrow0 = lrow0 * sc0 + sum0;
        lrow8 = lrow8 * sc8 + sum8;

#pragma unroll
        for (int j = 0; j < 16; j++) {
            ctxa[j][0] *= sc0; ctxa[j][1] *= sc0;
            ctxa[j][2] *= sc8; ctxa[j][3] *= sc8;
        }

        // ---- PV: ctx += p @ v^T (3-term) ----
        const uint32_t vb = base + 2 * KTILE + vboff;
#pragma unroll
        for (int g = 0; g < 4; g++) {
#pragma unroll
            for (int ng = 0; ng < 8; ng++) {
                uint32_t vh4[4], vl4[4];
                const uint32_t a = vb + (uint32_t)(ng * 16 * VSP * 2) + g * 32;
                ldm4(vh4, a);
                ldm4(vl4, a + VTILE);
                mma16816(ctxa[2 * ng + 0], ph[g], vh4 + 0);
                mma16816(ctxa[2 * ng + 0], pl[g], vh4 + 0);
                mma16816(ctxa[2 * ng + 0], ph[g], vl4 + 0);
                mma16816(ctxa[2 * ng + 1], ph[g], vh4 + 2);
                mma16816(ctxa[2 * ng + 1], pl[g], vh4 + 2);
                mma16816(ctxa[2 * ng + 1], ph[g], vl4 + 2);
            }
        }
        __syncthreads();
        load_kv(i + 2);
    }

    // ---- epilogue: normalize + split-store ctx ----
    const float inv0 = 1.0f / lrow0, inv8 = 1.0f / lrow8;
    const int r0 = m0 + w * 16 + (lane >> 2);
#pragma unroll
    for (int j = 0; j < 16; j++) {
        const int col = h * HD + j * 8 + cquad;
        const size_t i0 = ((size_t)b * SS + r0) * DOUT + col;
        const size_t i8 = ((size_t)b * SS + r0 + 8) * DOUT + col;
        split2(ctxa[j][0] * inv0, ctxa[j][1] * inv0, ctxh, ctxl, i0);
        split2(ctxa[j][2] * inv8, ctxa[j][3] * inv8, ctxh, ctxl, i8);
    }
}

// ---------------- prep kernels ----------------
__global__ void k_split(const float* __restrict__ in, bf* __restrict__ hi,
                        bf* __restrict__ lo, int n)
{
    const int i = (blockIdx.x * blockDim.x + threadIdx.x) * 2;
    if (i < n) {
        float2 v = *reinterpret_cast<const float2*>(in + i);
        split2(v.x, v.y, hi, lo, (size_t)i);
    }
}

__global__ void k_tsplit(const float* __restrict__ in, int ldin,
                         bf* __restrict__ oh, bf* __restrict__ ol, int ldout)
{
    __shared__ float t[32][33];
    const int c0 = blockIdx.x * 32, r0 = blockIdx.y * 32;
    const int tx = threadIdx.x, ty = threadIdx.y;
#pragma unroll
    for (int i = 0; i < 32; i += 8)
        t[ty + i][tx] = in[(size_t)(r0 + ty + i) * ldin + c0 + tx];
    __syncthreads();
#pragma unroll
    for (int i = 0; i < 32; i += 8) {
        const float v = t[tx][ty + i];
        const size_t idx = (size_t)(c0 + ty + i) * ldout + r0 + tx;
        bf h = __float2bfloat16(v);
        oh[idx] = h;
        ol[idx] = __float2bfloat16(v - __bfloat162float(h));
    }
}

__global__ void k_vtrans(const float* __restrict__ vp,
                         bf* __restrict__ oh, bf* __restrict__ ol)
{
    __shared__ float t[32][33];
    const int z = blockIdx.z;
    const int b = z / KVH, kv = z % KVH;
    const float* ip = vp + (size_t)b * SS * DKV + kv * HD;
    const size_t obase = (size_t)z * HD * SS;
    const int c0 = blockIdx.x * 32, r0 = blockIdx.y * 32;
    const int tx = threadIdx.x, ty = threadIdx.y;
#pragma unroll
    for (int i = 0; i < 32; i += 8)
        t[ty + i][tx] = ip[(size_t)(r0 + ty + i) * DKV + c0 + tx];
    __syncthreads();
#pragma unroll
    for (int i = 0; i < 32; i += 8) {
        const float v = t[tx][ty + i];
        const size_t idx = obase + (size_t)(c0 + ty + i) * SS + r0 + tx;
        bf h = __float2bfloat16(v);
        oh[idx] = h;
        ol[idx] = __float2bfloat16(v - __bfloat162float(h));
    }
}

__global__ void k_normrope(const float* __restrict__ in,
                           bf* __restrict__ oh, bf* __restrict__ ol,
                           const float* __restrict__ cosb,
                           const float* __restrict__ sinb,
                           const float* __restrict__ scale,
                           int nheads, float alpha)
{
    const int idx = blockIdx.x;
    const int h   = idx % nheads;
    const int bs  = idx / nheads;
    const int b   = bs / SS;
    const int pos = bs % SS;
    const int d   = threadIdx.x;

    float x = in[(size_t)bs * (nheads * HD) + h * HD + d];

    __shared__ float red[4];
    float v = x * x;
#pragma unroll
    for (int o = 16; o; o >>= 1) v += __shfl_xor_sync(0xffffffffu, v, o);
    if ((d & 31) == 0) red[d >> 5] = v;
    __syncthreads();
    const float ms = (red[0] + red[1] + red[2] + red[3]) * (1.0f / HD);
    const float xn = x * rsqrtf(ms + 1e-6f) * scale[d];

    __shared__ float sh[HD];
    sh[d] = xn;
    __syncthreads();
    const float rot = (d < HD / 2) ? -sh[d + HD / 2] : sh[d - HD / 2];
    const float o = (xn * cosb[pos * HD + d] + rot * sinb[pos * HD + d]) * alpha;
    const size_t oidx = ((size_t)(b * nheads + h) * SS + pos) * HD + d;
    bf hh = __float2bfloat16(o);
    oh[oidx] = hh;
    ol[oidx] = __float2bfloat16(o - __bfloat162float(hh));
}

// ---------------- launch ----------------
extern "C" void kernel_launch(void* const* d_in, const int* in_sizes, int n_in,
                              void* d_out, int out_size)
{
    const float* x    = (const float*)d_in[0];
    const float* cosb = (const float*)d_in[2];
    const float* sinb = (const float*)d_in[3];
    const float* Wq   = (const float*)d_in[4];
    const float* Wk   = (const float*)d_in[5];
    const float* Wv   = (const float*)d_in[6];
    const float* Wo   = (const float*)d_in[7];
    const float* qs   = (const float*)d_in[8];
    const float* ks   = (const float*)d_in[9];
    float* out = (float*)d_out;

    float *qp, *kp, *vp;
    bf *xh, *xl, *WqTh, *WqTl, *WkTh, *WkTl, *WvTh, *WvTl, *WoTh, *WoTl;
    bf *qhmh, *qhml, *khmh, *khml, *vTh, *vTl, *ctxh, *ctxl;
    cudaGetSymbolAddress((void**)&qp,   g_qp);
    cudaGetSymbolAddress((void**)&kp,   g_kp);
    cudaGetSymbolAddress((void**)&vp,   g_vp);
    cudaGetSymbolAddress((void**)&xh,   g_xh);
    cudaGetSymbolAddress((void**)&xl,   g_xl);
    cudaGetSymbolAddress((void**)&WqTh, g_WqTh);
    cudaGetSymbolAddress((void**)&WqTl, g_WqTl);
    cudaGetSymbolAddress((void**)&WkTh, g_WkTh);
    cudaGetSymbolAddress((void**)&WkTl, g_WkTl);
    cudaGetSymbolAddress((void**)&WvTh, g_WvTh);
    cudaGetSymbolAddress((void**)&WvTl, g_WvTl);
    cudaGetSymbolAddress((void**)&WoTh, g_WoTh);
    cudaGetSymbolAddress((void**)&WoTl, g_WoTl);
    cudaGetSymbolAddress((void**)&qhmh, g_qhmh);
    cudaGetSymbolAddress((void**)&qhml, g_qhml);
    cudaGetSymbolAddress((void**)&khmh, g_khmh);
    cudaGetSymbolAddress((void**)&khml, g_khml);
    cudaGetSymbolAddress((void**)&vTh,  g_vTh);
    cudaGetSymbolAddress((void**)&vTl,  g_vTl);
    cudaGetSymbolAddress((void**)&ctxh, g_ctxh);
    cudaGetSymbolAddress((void**)&ctxl, g_ctxl);

    cudaFuncSetAttribute(k_mma_dense, cudaFuncAttributeMaxDynamicSharedMemorySize, SMEM_DYN);
    cudaFuncSetAttribute(k_attn,      cudaFuncAttributeMaxDynamicSharedMemorySize, FSMEM);

    const dim3 tb(32, 8);

    // Prep: transpose+split weights, split x
    k_tsplit<<<dim3(DOUT / 32, DIN / 32), tb>>>(Wq, DOUT, WqTh, WqTl, DIN);
    k_tsplit<<<dim3(DKV  / 32, DIN / 32), tb>>>(Wk, DKV,  WkTh, WkTl, DIN);
    k_tsplit<<<dim3(DKV  / 32, DIN / 32), tb>>>(Wv, DKV,  WvTh, WvTl, DIN);
    k_tsplit<<<dim3(DIN / 32, DOUT / 32), tb>>>(Wo, DIN,  WoTh, WoTl, DOUT);
    k_split<<<(BS * DIN / 2 + 255) / 256, 256>>>(x, xh, xl, BS * DIN);

    // Projections (NT)
    k_mma_dense<<<dim3(DOUT / BN, BS / BM), NTHR, SMEM_DYN>>>(
        xh, xl, DIN, WqTh, WqTl, DIN, qp, DOUT, DIN);
    k_mma_dense<<<dim3(DKV / BN, BS / BM), NTHR, SMEM_DYN>>>(
        xh, xl, DIN, WkTh, WkTl, DIN, kp, DKV, DIN);
    k_mma_dense<<<dim3(DKV / BN, BS / BM), NTHR, SMEM_DYN>>>(
        xh, xl, DIN, WvTh, WvTl, DIN, vp, DKV, DIN);

    // RMSNorm + RoPE + head-major + split (1/sqrt(hd) folded into q)
    k_normrope<<<BS * NH,  HD>>>(qp, qhmh, qhml, cosb, sinb, qs, NH,
                                 0.08838834764831845f);
    k_normrope<<<BS * KVH, HD>>>(kp, khmh, khml, cosb, sinb, ks, KVH, 1.0f);

    // V transpose + split
    k_vtrans<<<dim3(HD / 32, SS / 32, BB * KVH), tb>>>(vp, vTh, vTl);

    // Fused flash attention
    k_attn<<<dim3(SS / FBM, BB * NH), 256, FSMEM>>>(
        qhmh, qhml, khmh, khml, vTh, vTl, ctxh, ctxl);

    // Output projection
    k_mma_dense<<<dim3(DIN / BN, BS / BM), NTHR, SMEM_DYN>>>(
        ctxh, ctxl, DOUT, WoTh, WoTl, DOUT, out, DIN, DOUT);
}